// round 15
// baseline (speedup 1.0000x reference)
#include <cuda_runtime.h>
#include <cuda_fp16.h>
#include <cstdint>

#define N_NODES 4096
#define NS 128
#define NV 16
#define H 8
#define D 16
#define COMB 144
#define HD 128   // H*D

typedef unsigned long long u64;

// ---- f16 mma, fp32 accumulate ----
__device__ __forceinline__ void mma_f16(float* d, const uint32_t* a, uint32_t b0, uint32_t b1) {
    asm("mma.sync.aligned.m16n8k16.row.col.f32.f16.f16.f32 "
        "{%0,%1,%2,%3},{%4,%5,%6,%7},{%8,%9},{%0,%1,%2,%3};"
        : "+f"(d[0]), "+f"(d[1]), "+f"(d[2]), "+f"(d[3])
        : "r"(a[0]), "r"(a[1]), "r"(a[2]), "r"(a[3]), "r"(b0), "r"(b1));
}
// ---- f16 mma, f16 accumulate (attn scores) ----
__device__ __forceinline__ void mma_f16_s(uint32_t& d0, uint32_t& d1, const uint32_t* a,
                                          uint32_t b0, uint32_t b1) {
    asm("mma.sync.aligned.m16n8k16.row.col.f16.f16.f16.f16 "
        "{%0,%1},{%2,%3,%4,%5},{%6,%7},{%8,%9};"
        : "=r"(d0), "=r"(d1)
        : "r"(a[0]), "r"(a[1]), "r"(a[2]), "r"(a[3]), "r"(b0), "r"(b1),
          "r"(0u), "r"(0u));
}
__device__ __forceinline__ uint32_t h2bits(__half2 h) {
    return *reinterpret_cast<uint32_t*>(&h);
}
__device__ __forceinline__ __half2 bits2h(uint32_t u) {
    return *reinterpret_cast<__half2*>(&u);
}
// ---- cp.async ----
__device__ __forceinline__ uint32_t smem_u32(const void* p) {
    uint32_t a;
    asm("{ .reg .u64 t; cvta.to.shared.u64 t, %1; cvt.u32.u64 %0, t; }" : "=r"(a) : "l"(p));
    return a;
}
__device__ __forceinline__ void cp16(uint32_t smem_dst, const void* gsrc) {
    asm volatile("cp.async.cg.shared.global [%0], [%1], 16;" :: "r"(smem_dst), "l"(gsrc));
}
__device__ __forceinline__ void cp_commit() { asm volatile("cp.async.commit_group;"); }
template <int N>
__device__ __forceinline__ void cp_wait() {
    asm volatile("cp.async.wait_group %0;" :: "n"(N) : "memory");
}

// Scratch (static device globals)
__device__ __half g_qh[N_NODES * HD];     // q * (D^-0.5 * log2e)
__device__ __half g_kh[N_NODES * HD];
__device__ __half g_vth[HD * N_NODES];    // v TRANSPOSED [ch][node]
__device__ __half g_attn_h[N_NODES * HD]; // attention output O, f16
__device__ __half g_Wqk_t[256 * COMB];    // TRANSPOSED [n=q|k][k=144]
__device__ __half g_Wv_t[HD * NS];        // TRANSPOSED [n][k]
__device__ __half g_Wo_t[NS * HD];        // TRANSPOSED [n][k]

// ---------------------------------------------------------------------------
// Kernel 0: one-off f32 -> f16 TRANSPOSED weight conversion.
// ---------------------------------------------------------------------------
__global__ void convw_kernel(const float* __restrict__ Wq, const float* __restrict__ Wk,
                             const float* __restrict__ Wv, const float* __restrict__ Wo) {
    const int n = blockIdx.x;     // 0..255
    const int k = threadIdx.x;    // 0..143
    const float w = (n < 128) ? Wq[k * 128 + n] : Wk[k * 128 + (n - 128)];
    g_Wqk_t[n * COMB + k] = __float2half(w);
    if (n < 128 && k < 128) {
        g_Wv_t[n * NS + k] = __float2half(Wv[k * 128 + n]);
        g_Wo_t[n * HD + k] = __float2half(Wo[k * 128 + n]);
    }
}

// ---------------------------------------------------------------------------
// Kernel 1: tensor-core projections (R11–R14, unchanged — proven fragments).
// ---------------------------------------------------------------------------
#define SA 168
#define SWT 12
#define SV 138
__global__ __launch_bounds__(256) void proj_kernel(
        const float* __restrict__ s, const float* __restrict__ v,
        const float* __restrict__ bq, const float* __restrict__ bk,
        const float* __restrict__ bv) {
    const int nb = blockIdx.x * 32;
    const int t = threadIdx.x;
    const int w = t >> 5, lane = t & 31;
    const int mw = w >> 2, nw = w & 3;
    const int g = lane >> 2, tid = lane & 3;
    const int m0 = mw * 16;

    __shared__ __align__(16) __half comb[32 * SA];
    __shared__ __align__(16) uint32_t wtb[2][256 * SWT];
    __shared__ __align__(16) __half vsm[32 * SV];

    for (int i = t; i < 32 * 32; i += 256) {
        const int node = i >> 5, c4 = i & 31;
        const float4 s4 = ((const float4*)(s + (nb + node) * NS))[c4];
        __half2* dst = (__half2*)(comb + node * SA + c4 * 4);
        dst[0] = __floats2half2_rn(s4.x, s4.y);
        dst[1] = __floats2half2_rn(s4.z, s4.w);
    }
    for (int i = t; i < 32 * NV; i += 256) {
        const int node = i >> 4, vi = i & 15;
        const float* vp = v + (nb + node) * NV * 3 + vi * 3;
        const float x = vp[0], y = vp[1], z = vp[2];
        comb[node * SA + 128 + vi] = __float2half(sqrtf(fmaxf(x * x + y * y + z * z, 1e-8f)));
    }

    const uint32_t* cw = (const uint32_t*)comb;
    const uint32_t wb[2] = { smem_u32(wtb[0]), smem_u32(wtb[1]) };

    float cq[8][4];
#pragma unroll
    for (int i = 0; i < 8; i++)
#pragma unroll
        for (int j = 0; j < 4; j++) cq[i][j] = 0.f;

    {
#pragma unroll
        for (int p = 0; p < 2; p++) {
            const int cid = t + p * 256;
            const int r = cid >> 1, hf = cid & 1;
            cp16(wb[0] + r * 48 + hf * 16,
                 (const char*)g_Wqk_t + r * (COMB * 2) + hf * 16);
        }
        cp_commit();
    }
    __syncthreads();

    for (int ks = 0; ks < 9; ks++) {
        if (ks < 8) {
            const uint32_t dst = wb[(ks + 1) & 1];
#pragma unroll
            for (int p = 0; p < 2; p++) {
                const int cid = t + p * 256;
                const int r = cid >> 1, hf = cid & 1;
                cp16(dst + r * 48 + hf * 16,
                     (const char*)g_Wqk_t + r * (COMB * 2) + (ks + 1) * 32 + hf * 16);
            }
            cp_commit();
            cp_wait<1>();
        } else {
            cp_wait<0>();
        }
        __syncthreads();
        const uint32_t* wt = wtb[ks & 1];

        uint32_t a[4];
        a[0] = cw[(m0 + g) * 84 + ks * 8 + tid];
        a[1] = cw[(m0 + g + 8) * 84 + ks * 8 + tid];
        a[2] = cw[(m0 + g) * 84 + ks * 8 + 4 + tid];
        a[3] = cw[(m0 + g + 8) * 84 + ks * 8 + 4 + tid];
#pragma unroll
        for (int bt = 0; bt < 8; bt++) {
            const uint32_t* br = wt + (nw * 64 + bt * 8 + g) * SWT;
            mma_f16(cq[bt], a, br[tid], br[4 + tid]);
        }
        __syncthreads();
    }

    {
        const float* barr = (nw < 2) ? bq : bk;
        const float scale = (nw < 2) ? 0.25f * 1.4426950408889634f : 1.0f;
        __half* dst = (nw < 2) ? g_qh : g_kh;
#pragma unroll
        for (int bt = 0; bt < 8; bt++) {
            const int c = nw * 64 + bt * 8 + 2 * tid;
            const int cl = c & 127;
            const float b0 = barr[cl], b1 = barr[cl + 1];
            const int r0 = nb + m0 + g;
            *(__half2*)(dst + r0 * HD + cl) =
                __floats2half2_rn((cq[bt][0] + b0) * scale, (cq[bt][1] + b1) * scale);
            *(__half2*)(dst + (r0 + 8) * HD + cl) =
                __floats2half2_rn((cq[bt][2] + b0) * scale, (cq[bt][3] + b1) * scale);
        }
    }

    float cv[4][4];
#pragma unroll
    for (int i = 0; i < 4; i++)
#pragma unroll
        for (int j = 0; j < 4; j++) cv[i][j] = 0.f;

    {
        const int r = t >> 1, hf = t & 1;
        cp16(wb[0] + r * 48 + hf * 16,
             (const char*)g_Wv_t + r * (NS * 2) + hf * 16);
        cp_commit();
    }
    for (int ks = 0; ks < 8; ks++) {
        if (ks < 7) {
            const uint32_t dst = wb[(ks + 1) & 1];
            const int r = t >> 1, hf = t & 1;
            cp16(dst + r * 48 + hf * 16,
                 (const char*)g_Wv_t + r * (NS * 2) + (ks + 1) * 32 + hf * 16);
            cp_commit();
            cp_wait<1>();
        } else {
            cp_wait<0>();
        }
        __syncthreads();
        const uint32_t* wt = wtb[ks & 1];

        uint32_t a[4];
        a[0] = cw[(m0 + g) * 84 + ks * 8 + tid];
        a[1] = cw[(m0 + g + 8) * 84 + ks * 8 + tid];
        a[2] = cw[(m0 + g) * 84 + ks * 8 + 4 + tid];
        a[3] = cw[(m0 + g + 8) * 84 + ks * 8 + 4 + tid];
#pragma unroll
        for (int bt = 0; bt < 4; bt++) {
            const uint32_t* br = wt + (nw * 32 + bt * 8 + g) * SWT;
            mma_f16(cv[bt], a, br[tid], br[4 + tid]);
        }
        __syncthreads();
    }

#pragma unroll
    for (int bt = 0; bt < 4; bt++) {
        const int c = nw * 32 + bt * 8 + 2 * tid;
        const float b0 = bv[c], b1 = bv[c + 1];
        const int r0 = m0 + g;
        *(__half2*)(vsm + r0 * SV + c)       = __floats2half2_rn(cv[bt][0] + b0, cv[bt][1] + b1);
        *(__half2*)(vsm + (r0 + 8) * SV + c) = __floats2half2_rn(cv[bt][2] + b0, cv[bt][3] + b1);
    }
    __syncthreads();
    {
        const int d = t >> 1;
        const int npart = (t & 1) * 16;
#pragma unroll
        for (int i = 0; i < 8; i++) {
            const int node = npart + i * 2;
            __half2 p;
            p.x = vsm[node * SV + d];
            p.y = vsm[(node + 1) * SV + d];
            *(__half2*)(g_vth + d * N_NODES + nb + node) = p;
        }
    }
}

// ---------------------------------------------------------------------------
// Kernel 2: f16 mma flash attention, 128 queries/block (R14 champion).
// ---------------------------------------------------------------------------
__global__ __launch_bounds__(256) void attn_kernel() {
    const int h = blockIdx.y;
    const int qbase = blockIdx.x * 128;
    const int t = threadIdx.x;      // 0..255
    const int w = t >> 5;
    const int lane = t & 31;
    const int g = lane >> 2;
    const int tid = lane & 3;

    __shared__ __align__(16) uint32_t Ksw[2][128 * 12];
    __shared__ __align__(16) uint32_t Vsw[2][16 * 68];

    uint32_t qa[4];
    {
        const __half* Q0 = g_qh + (qbase + w * 16 + g) * HD + h * D;
        const __half* Q1 = Q0 + 8 * HD;
        qa[0] = *(const uint32_t*)(Q0 + 2 * tid);
        qa[1] = *(const uint32_t*)(Q1 + 2 * tid);
        qa[2] = *(const uint32_t*)(Q0 + 2 * tid + 8);
        qa[3] = *(const uint32_t*)(Q1 + 2 * tid + 8);
    }

    float o0[4] = {0.f, 0.f, 0.f, 0.f};
    float o1[4] = {0.f, 0.f, 0.f, 0.f};
    float l0 = 0.f, l1 = 0.f;

    const bool stageK = (t < 128);
    const int sk_key = t & 127;
    const int sv_row = (t & 127) >> 3;
    const int sv_c   = (t & 7);
    const uint32_t kdst[2] = { smem_u32(Ksw[0]) + sk_key * 48,
                               smem_u32(Ksw[1]) + sk_key * 48 };
    const uint32_t vdst[2] = { smem_u32(Vsw[0]) + (sv_row * 68 + sv_c * 8) * 4,
                               smem_u32(Vsw[1]) + (sv_row * 68 + sv_c * 8) * 4 };

    if (stageK) {
        const __half* kp = g_kh + sk_key * HD + h * D;
        cp16(kdst[0], kp);
        cp16(kdst[0] + 16, kp + 8);
    } else {
        const __half* vp = g_vth + (h * D + sv_row) * N_NODES + sv_c * 16;
        cp16(vdst[0], vp);
        cp16(vdst[0] + 16, vp + 8);
    }
    cp_commit();

    for (int i = 0; i < 32; i++) {
        const int b = i & 1;
        if (i < 31) {
            const int kt = (i + 1) * 128;
            const int nb_ = (i + 1) & 1;
            if (stageK) {
                const __half* kp = g_kh + (kt + sk_key) * HD + h * D;
                cp16(kdst[nb_], kp);
                cp16(kdst[nb_] + 16, kp + 8);
            } else {
                const __half* vp = g_vth + (h * D + sv_row) * N_NODES + kt + sv_c * 16;
                cp16(vdst[nb_], vp);
                cp16(vdst[nb_] + 16, vp + 8);
            }
            cp_commit();
            cp_wait<1>();
        } else {
            cp_wait<0>();
        }
        __syncthreads();

        const uint32_t* Kg = Ksw[b];
        const uint32_t* Vg = Vsw[b];
        __half2 lh0 = __half2half2(__float2half(0.f));
        __half2 lh1 = lh0;
#pragma unroll
        for (int u = 0; u < 8; u++) {
            uint32_t sA0, sA1, sB0, sB1;
            const int kA = (16 * u + g) * 12;
            const int kB = (16 * u + 8 + g) * 12;
            mma_f16_s(sA0, sA1, qa, Kg[kA + tid], Kg[kA + 4 + tid]);
            mma_f16_s(sB0, sB1, qa, Kg[kB + tid], Kg[kB + 4 + tid]);
            const __half2 e0 = h2exp2(bits2h(sA0));
            const __half2 e1 = h2exp2(bits2h(sA1));
            const __half2 e2 = h2exp2(bits2h(sB0));
            const __half2 e3 = h2exp2(bits2h(sB1));
            lh0 = __hadd2(lh0, __hadd2(e0, e2));
            lh1 = __hadd2(lh1, __hadd2(e1, e3));
            uint32_t pa[4];
            pa[0] = h2bits(e0);
            pa[1] = h2bits(e1);
            pa[2] = h2bits(e2);
            pa[3] = h2bits(e3);
            const int vb = 8 * u + tid;
            mma_f16(o0, pa, Vg[g * 68 + vb],       Vg[g * 68 + 4 + vb]);
            mma_f16(o1, pa, Vg[(g + 8) * 68 + vb], Vg[(g + 8) * 68 + 4 + vb]);
        }
        const float2 f0 = __half22float2(lh0);
        const float2 f1 = __half22float2(lh1);
        l0 += f0.x + f0.y;
        l1 += f1.x + f1.y;

        __syncthreads();
    }

    l0 += __shfl_xor_sync(0xffffffffu, l0, 1);
    l0 += __shfl_xor_sync(0xffffffffu, l0, 2);
    l1 += __shfl_xor_sync(0xffffffffu, l1, 1);
    l1 += __shfl_xor_sync(0xffffffffu, l1, 2);
    const float i0 = 1.f / l0;
    const float i1 = 1.f / l1;

    __half* O0 = g_attn_h + (qbase + w * 16 + g) * HD + h * D;
    __half* O1 = O0 + 8 * HD;
    *(__half2*)(O0 + 2 * tid)     = __floats2half2_rn(o0[0] * i0, o0[1] * i0);
    *(__half2*)(O1 + 2 * tid)     = __floats2half2_rn(o0[2] * i1, o0[3] * i1);
    *(__half2*)(O0 + 2 * tid + 8) = __floats2half2_rn(o1[0] * i0, o1[1] * i0);
    *(__half2*)(O1 + 2 * tid + 8) = __floats2half2_rn(o1[2] * i1, o1[3] * i1);
}

// ---------------------------------------------------------------------------
// Kernel 3: out projection — Wo B-fragments REGISTER-RESIDENT (64 direct LDG
// per thread, fully MLP-overlapped, L2-resident). No Wo smem stage: smem is
// just the 8.5KB O tile + 8.3KB vals -> high residency, short critical path.
// 16 nodes/block, 128 threads, grid 256.
// ---------------------------------------------------------------------------
__global__ __launch_bounds__(128) void out_kernel(
        const float* __restrict__ s, const float* __restrict__ vin,
        const float* __restrict__ bo,
        const float* __restrict__ gamma, const float* __restrict__ beta,
        float* __restrict__ out) {
    __shared__ __align__(16) __half osm[16 * SA];   // 16 x 84-word rows
    __shared__ float vals[16 * 129];
    __shared__ float mus[16], ivs[16];

    const int nb = blockIdx.x * 16;
    const int t = threadIdx.x;       // 0..127
    const int w = t >> 5, lane = t & 31;   // w = n-slice
    const int g = lane >> 2, tid = lane & 3;

    // v passthrough
    {
        const float4* vsrc = (const float4*)vin + blockIdx.x * 192;
        float4* vdst = (float4*)(out + N_NODES * NS) + blockIdx.x * 192;
        for (int i = t; i < 192; i += 128) vdst[i] = vsrc[i];
    }

    // stage O tile via cp.async (256 chunks, 2/thread)
    const uint32_t ob = smem_u32(osm);
    for (int i = t; i < 256; i += 128) {
        const int r = i >> 4, c = i & 15;
        cp16(ob + r * 336 + c * 16, g_attn_h + (nb + r) * HD + c * 8);
    }
    cp_commit();

    // Wo B-fragments straight to registers: 64 independent LDG.32
    uint32_t wreg[8][8];   // [ks][bt*2 + {0,1}]
    {
        const uint32_t* wg = (const uint32_t*)g_Wo_t;
#pragma unroll
        for (int ks = 0; ks < 8; ks++) {
#pragma unroll
            for (int bt = 0; bt < 4; bt++) {
                const uint32_t* br = wg + (w * 32 + bt * 8 + g) * 64 + ks * 8;
                wreg[ks][bt * 2]     = __ldg(br + tid);
                wreg[ks][bt * 2 + 1] = __ldg(br + 4 + tid);
            }
        }
    }

    // residual s (f32)
    for (int i = t; i < 16 * 128; i += 128) {
        const int node = i >> 7, c = i & 127;
        vals[node * 129 + c] = s[(nb + node) * NS + c];
    }

    cp_wait<0>();
    __syncthreads();

    const uint32_t* cw = (const uint32_t*)osm;
    float cq[4][4];
#pragma unroll
    for (int i = 0; i < 4; i++)
#pragma unroll
        for (int j = 0; j < 4; j++) cq[i][j] = 0.f;

#pragma unroll
    for (int ks = 0; ks < 8; ks++) {
        uint32_t a[4];
        a[0] = cw[g * 84 + ks * 8 + tid];
        a[1] = cw[(g + 8) * 84 + ks * 8 + tid];
        a[2] = cw[g * 84 + ks * 8 + 4 + tid];
        a[3] = cw[(g + 8) * 84 + ks * 8 + 4 + tid];
#pragma unroll
        for (int bt = 0; bt < 4; bt++) {
            mma_f16(cq[bt], a, wreg[ks][bt * 2], wreg[ks][bt * 2 + 1]);
        }
    }

    // epilogue: vals += attn_out + bias
#pragma unroll
    for (int bt = 0; bt < 4; bt++) {
        const int c = w * 32 + bt * 8 + 2 * tid;
        const float b0 = bo[c], b1 = bo[c + 1];
        vals[g * 129 + c]           += cq[bt][0] + b0;
        vals[g * 129 + c + 1]       += cq[bt][1] + b1;
        vals[(g + 8) * 129 + c]     += cq[bt][2] + b0;
        vals[(g + 8) * 129 + c + 1] += cq[bt][3] + b1;
    }
    __syncthreads();

    // LayerNorm: warp w owns nodes 4w .. 4w+3
#pragma unroll
    for (int jj = 0; jj < 4; jj++) {
        const int j = w * 4 + jj;
        float sv = 0.f, sq = 0.f;
#pragma unroll
        for (int c = 0; c < 4; c++) {
            const float x = vals[j * 129 + lane + 32 * c];
            sv += x;
            sq = fmaf(x, x, sq);
        }
#pragma unroll
        for (int off = 16; off > 0; off >>= 1) {
            sv += __shfl_xor_sync(0xffffffffu, sv, off);
            sq += __shfl_xor_sync(0xffffffffu, sq, off);
        }
        if (lane == 0) {
            const float mu = sv * (1.f / 128.f);
            mus[j] = mu;
            ivs[j] = rsqrtf(sq * (1.f / 128.f) - mu * mu + 1e-5f);
        }
    }
    __syncthreads();

    for (int i = t; i < 16 * 128; i += 128) {
        const int node = i >> 7, c = i & 127;
        out[(nb + node) * NS + c] =
            (vals[node * 129 + c] - mus[node]) * ivs[node] * gamma[c] + beta[c];
    }
}

// ---------------------------------------------------------------------------
extern "C" void kernel_launch(void* const* d_in, const int* in_sizes, int n_in,
                              void* d_out, int out_size) {
    const float* s     = (const float*)d_in[0];
    const float* v     = (const float*)d_in[1];
    const float* Wq    = (const float*)d_in[2];
    const float* bq    = (const float*)d_in[3];
    const float* Wk    = (const float*)d_in[4];
    const float* bk    = (const float*)d_in[5];
    const float* Wv    = (const float*)d_in[6];
    const float* bv    = (const float*)d_in[7];
    const float* Wo    = (const float*)d_in[8];
    const float* bo    = (const float*)d_in[9];
    const float* gamma = (const float*)d_in[10];
    const float* beta  = (const float*)d_in[11];
    float* out = (float*)d_out;

    convw_kernel<<<256, 144>>>(Wq, Wk, Wv, Wo);
    proj_kernel<<<N_NODES / 32, 256>>>(s, v, bq, bk, bv);
    attn_kernel<<<dim3(N_NODES / 128, H), 256>>>();
    out_kernel<<<N_NODES / 16, 128>>>(s, v, bo, gamma, beta, out);
}

// round 17
// speedup vs baseline: 1.0579x; 1.0579x over previous
#include <cuda_runtime.h>
#include <cuda_fp16.h>
#include <cstdint>

#define N_NODES 4096
#define NS 128
#define NV 16
#define H 8
#define D 16
#define COMB 144
#define HD 128   // H*D

typedef unsigned long long u64;

// ---- f16 mma, fp32 accumulate ----
__device__ __forceinline__ void mma_f16(float* d, const uint32_t* a, uint32_t b0, uint32_t b1) {
    asm("mma.sync.aligned.m16n8k16.row.col.f32.f16.f16.f32 "
        "{%0,%1,%2,%3},{%4,%5,%6,%7},{%8,%9},{%0,%1,%2,%3};"
        : "+f"(d[0]), "+f"(d[1]), "+f"(d[2]), "+f"(d[3])
        : "r"(a[0]), "r"(a[1]), "r"(a[2]), "r"(a[3]), "r"(b0), "r"(b1));
}
// ---- f16 mma, f16 accumulate (attn scores) ----
__device__ __forceinline__ void mma_f16_s(uint32_t& d0, uint32_t& d1, const uint32_t* a,
                                          uint32_t b0, uint32_t b1) {
    asm("mma.sync.aligned.m16n8k16.row.col.f16.f16.f16.f16 "
        "{%0,%1},{%2,%3,%4,%5},{%6,%7},{%8,%9};"
        : "=r"(d0), "=r"(d1)
        : "r"(a[0]), "r"(a[1]), "r"(a[2]), "r"(a[3]), "r"(b0), "r"(b1),
          "r"(0u), "r"(0u));
}
__device__ __forceinline__ uint32_t h2bits(__half2 h) {
    return *reinterpret_cast<uint32_t*>(&h);
}
__device__ __forceinline__ __half2 bits2h(uint32_t u) {
    return *reinterpret_cast<__half2*>(&u);
}
// ---- cp.async ----
__device__ __forceinline__ uint32_t smem_u32(const void* p) {
    uint32_t a;
    asm("{ .reg .u64 t; cvta.to.shared.u64 t, %1; cvt.u32.u64 %0, t; }" : "=r"(a) : "l"(p));
    return a;
}
__device__ __forceinline__ void cp16(uint32_t smem_dst, const void* gsrc) {
    asm volatile("cp.async.cg.shared.global [%0], [%1], 16;" :: "r"(smem_dst), "l"(gsrc));
}
__device__ __forceinline__ void cp_commit() { asm volatile("cp.async.commit_group;"); }
template <int N>
__device__ __forceinline__ void cp_wait() {
    asm volatile("cp.async.wait_group %0;" :: "n"(N) : "memory");
}

// Scratch (static device globals)
__device__ __half g_qh[N_NODES * HD];     // q * (D^-0.5 * log2e)
__device__ __half g_kh[N_NODES * HD];
__device__ __half g_vth[HD * N_NODES];    // v TRANSPOSED [ch][node]
__device__ __half g_attn_h[N_NODES * HD]; // attention output O, f16
__device__ __half g_Wqk_t[256 * COMB];    // TRANSPOSED [n=q|k][k=144]
__device__ __half g_Wv_t[HD * NS];        // TRANSPOSED [n][k]
__device__ __half g_Wo_t[NS * HD];        // TRANSPOSED [n][k]

// ---------------------------------------------------------------------------
// Kernel 0: one-off f32 -> f16 TRANSPOSED weight conversion.
// ---------------------------------------------------------------------------
__global__ void convw_kernel(const float* __restrict__ Wq, const float* __restrict__ Wk,
                             const float* __restrict__ Wv, const float* __restrict__ Wo) {
    const int n = blockIdx.x;     // 0..255
    const int k = threadIdx.x;    // 0..143
    const float w = (n < 128) ? Wq[k * 128 + n] : Wk[k * 128 + (n - 128)];
    g_Wqk_t[n * COMB + k] = __float2half(w);
    if (n < 128 && k < 128) {
        g_Wv_t[n * NS + k] = __float2half(Wv[k * 128 + n]);
        g_Wo_t[n * HD + k] = __float2half(Wo[k * 128 + n]);
    }
}

// ---------------------------------------------------------------------------
// Kernel 1: tensor-core projections (R11–R15 proven fragments) + v pass-
// through folded in. Block covers 32 nodes = 32*48 floats = 384 float4 of v
// (R16 bug: copied only 96 — fixed).
// ---------------------------------------------------------------------------
#define SA 168
#define SWT 12
#define SV 138
__global__ __launch_bounds__(256) void proj_kernel(
        const float* __restrict__ s, const float* __restrict__ v,
        const float* __restrict__ bq, const float* __restrict__ bk,
        const float* __restrict__ bv, float* __restrict__ out) {
    const int nb = blockIdx.x * 32;
    const int t = threadIdx.x;
    const int w = t >> 5, lane = t & 31;
    const int mw = w >> 2, nw = w & 3;
    const int g = lane >> 2, tid = lane & 3;
    const int m0 = mw * 16;

    __shared__ __align__(16) __half comb[32 * SA];
    __shared__ __align__(16) uint32_t wtb[2][256 * SWT];
    __shared__ __align__(16) __half vsm[32 * SV];

    // v passthrough: 32 nodes * 48 floats = 384 float4
    {
        const float4* vsrc = (const float4*)v + blockIdx.x * 384;
        float4* vdst = (float4*)(out + N_NODES * NS) + blockIdx.x * 384;
        for (int i = t; i < 384; i += 256) vdst[i] = vsrc[i];
    }

    for (int i = t; i < 32 * 32; i += 256) {
        const int node = i >> 5, c4 = i & 31;
        const float4 s4 = ((const float4*)(s + (nb + node) * NS))[c4];
        __half2* dst = (__half2*)(comb + node * SA + c4 * 4);
        dst[0] = __floats2half2_rn(s4.x, s4.y);
        dst[1] = __floats2half2_rn(s4.z, s4.w);
    }
    for (int i = t; i < 32 * NV; i += 256) {
        const int node = i >> 4, vi = i & 15;
        const float* vp = v + (nb + node) * NV * 3 + vi * 3;
        const float x = vp[0], y = vp[1], z = vp[2];
        comb[node * SA + 128 + vi] = __float2half(sqrtf(fmaxf(x * x + y * y + z * z, 1e-8f)));
    }

    const uint32_t* cw = (const uint32_t*)comb;
    const uint32_t wb[2] = { smem_u32(wtb[0]), smem_u32(wtb[1]) };

    float cq[8][4];
#pragma unroll
    for (int i = 0; i < 8; i++)
#pragma unroll
        for (int j = 0; j < 4; j++) cq[i][j] = 0.f;

    {
#pragma unroll
        for (int p = 0; p < 2; p++) {
            const int cid = t + p * 256;
            const int r = cid >> 1, hf = cid & 1;
            cp16(wb[0] + r * 48 + hf * 16,
                 (const char*)g_Wqk_t + r * (COMB * 2) + hf * 16);
        }
        cp_commit();
    }
    __syncthreads();

    for (int ks = 0; ks < 9; ks++) {
        if (ks < 8) {
            const uint32_t dst = wb[(ks + 1) & 1];
#pragma unroll
            for (int p = 0; p < 2; p++) {
                const int cid = t + p * 256;
                const int r = cid >> 1, hf = cid & 1;
                cp16(dst + r * 48 + hf * 16,
                     (const char*)g_Wqk_t + r * (COMB * 2) + (ks + 1) * 32 + hf * 16);
            }
            cp_commit();
            cp_wait<1>();
        } else {
            cp_wait<0>();
        }
        __syncthreads();
        const uint32_t* wt = wtb[ks & 1];

        uint32_t a[4];
        a[0] = cw[(m0 + g) * 84 + ks * 8 + tid];
        a[1] = cw[(m0 + g + 8) * 84 + ks * 8 + tid];
        a[2] = cw[(m0 + g) * 84 + ks * 8 + 4 + tid];
        a[3] = cw[(m0 + g + 8) * 84 + ks * 8 + 4 + tid];
#pragma unroll
        for (int bt = 0; bt < 8; bt++) {
            const uint32_t* br = wt + (nw * 64 + bt * 8 + g) * SWT;
            mma_f16(cq[bt], a, br[tid], br[4 + tid]);
        }
        __syncthreads();
    }

    {
        const float* barr = (nw < 2) ? bq : bk;
        const float scale = (nw < 2) ? 0.25f * 1.4426950408889634f : 1.0f;
        __half* dst = (nw < 2) ? g_qh : g_kh;
#pragma unroll
        for (int bt = 0; bt < 8; bt++) {
            const int c = nw * 64 + bt * 8 + 2 * tid;
            const int cl = c & 127;
            const float b0 = barr[cl], b1 = barr[cl + 1];
            const int r0 = nb + m0 + g;
            *(__half2*)(dst + r0 * HD + cl) =
                __floats2half2_rn((cq[bt][0] + b0) * scale, (cq[bt][1] + b1) * scale);
            *(__half2*)(dst + (r0 + 8) * HD + cl) =
                __floats2half2_rn((cq[bt][2] + b0) * scale, (cq[bt][3] + b1) * scale);
        }
    }

    float cv[4][4];
#pragma unroll
    for (int i = 0; i < 4; i++)
#pragma unroll
        for (int j = 0; j < 4; j++) cv[i][j] = 0.f;

    {
        const int r = t >> 1, hf = t & 1;
        cp16(wb[0] + r * 48 + hf * 16,
             (const char*)g_Wv_t + r * (NS * 2) + hf * 16);
        cp_commit();
    }
    for (int ks = 0; ks < 8; ks++) {
        if (ks < 7) {
            const uint32_t dst = wb[(ks + 1) & 1];
            const int r = t >> 1, hf = t & 1;
            cp16(dst + r * 48 + hf * 16,
                 (const char*)g_Wv_t + r * (NS * 2) + (ks + 1) * 32 + hf * 16);
            cp_commit();
            cp_wait<1>();
        } else {
            cp_wait<0>();
        }
        __syncthreads();
        const uint32_t* wt = wtb[ks & 1];

        uint32_t a[4];
        a[0] = cw[(m0 + g) * 84 + ks * 8 + tid];
        a[1] = cw[(m0 + g + 8) * 84 + ks * 8 + tid];
        a[2] = cw[(m0 + g) * 84 + ks * 8 + 4 + tid];
        a[3] = cw[(m0 + g + 8) * 84 + ks * 8 + 4 + tid];
#pragma unroll
        for (int bt = 0; bt < 4; bt++) {
            const uint32_t* br = wt + (nw * 32 + bt * 8 + g) * SWT;
            mma_f16(cv[bt], a, br[tid], br[4 + tid]);
        }
        __syncthreads();
    }

#pragma unroll
    for (int bt = 0; bt < 4; bt++) {
        const int c = nw * 32 + bt * 8 + 2 * tid;
        const float b0 = bv[c], b1 = bv[c + 1];
        const int r0 = m0 + g;
        *(__half2*)(vsm + r0 * SV + c)       = __floats2half2_rn(cv[bt][0] + b0, cv[bt][1] + b1);
        *(__half2*)(vsm + (r0 + 8) * SV + c) = __floats2half2_rn(cv[bt][2] + b0, cv[bt][3] + b1);
    }
    __syncthreads();
    {
        const int d = t >> 1;
        const int npart = (t & 1) * 16;
#pragma unroll
        for (int i = 0; i < 8; i++) {
            const int node = npart + i * 2;
            __half2 p;
            p.x = vsm[node * SV + d];
            p.y = vsm[(node + 1) * SV + d];
            *(__half2*)(g_vth + d * N_NODES + nb + node) = p;
        }
    }
}

// ---------------------------------------------------------------------------
// Kernel 2: f16 mma flash attention, 128 queries/block (R14 champion).
// ---------------------------------------------------------------------------
__global__ __launch_bounds__(256) void attn_kernel() {
    const int h = blockIdx.y;
    const int qbase = blockIdx.x * 128;
    const int t = threadIdx.x;      // 0..255
    const int w = t >> 5;
    const int lane = t & 31;
    const int g = lane >> 2;
    const int tid = lane & 3;

    __shared__ __align__(16) uint32_t Ksw[2][128 * 12];
    __shared__ __align__(16) uint32_t Vsw[2][16 * 68];

    uint32_t qa[4];
    {
        const __half* Q0 = g_qh + (qbase + w * 16 + g) * HD + h * D;
        const __half* Q1 = Q0 + 8 * HD;
        qa[0] = *(const uint32_t*)(Q0 + 2 * tid);
        qa[1] = *(const uint32_t*)(Q1 + 2 * tid);
        qa[2] = *(const uint32_t*)(Q0 + 2 * tid + 8);
        qa[3] = *(const uint32_t*)(Q1 + 2 * tid + 8);
    }

    float o0[4] = {0.f, 0.f, 0.f, 0.f};
    float o1[4] = {0.f, 0.f, 0.f, 0.f};
    float l0 = 0.f, l1 = 0.f;

    const bool stageK = (t < 128);
    const int sk_key = t & 127;
    const int sv_row = (t & 127) >> 3;
    const int sv_c   = (t & 7);
    const uint32_t kdst[2] = { smem_u32(Ksw[0]) + sk_key * 48,
                               smem_u32(Ksw[1]) + sk_key * 48 };
    const uint32_t vdst[2] = { smem_u32(Vsw[0]) + (sv_row * 68 + sv_c * 8) * 4,
                               smem_u32(Vsw[1]) + (sv_row * 68 + sv_c * 8) * 4 };

    if (stageK) {
        const __half* kp = g_kh + sk_key * HD + h * D;
        cp16(kdst[0], kp);
        cp16(kdst[0] + 16, kp + 8);
    } else {
        const __half* vp = g_vth + (h * D + sv_row) * N_NODES + sv_c * 16;
        cp16(vdst[0], vp);
        cp16(vdst[0] + 16, vp + 8);
    }
    cp_commit();

    for (int i = 0; i < 32; i++) {
        const int b = i & 1;
        if (i < 31) {
            const int kt = (i + 1) * 128;
            const int nb_ = (i + 1) & 1;
            if (stageK) {
                const __half* kp = g_kh + (kt + sk_key) * HD + h * D;
                cp16(kdst[nb_], kp);
                cp16(kdst[nb_] + 16, kp + 8);
            } else {
                const __half* vp = g_vth + (h * D + sv_row) * N_NODES + kt + sv_c * 16;
                cp16(vdst[nb_], vp);
                cp16(vdst[nb_] + 16, vp + 8);
            }
            cp_commit();
            cp_wait<1>();
        } else {
            cp_wait<0>();
        }
        __syncthreads();

        const uint32_t* Kg = Ksw[b];
        const uint32_t* Vg = Vsw[b];
        __half2 lh0 = __half2half2(__float2half(0.f));
        __half2 lh1 = lh0;
#pragma unroll
        for (int u = 0; u < 8; u++) {
            uint32_t sA0, sA1, sB0, sB1;
            const int kA = (16 * u + g) * 12;
            const int kB = (16 * u + 8 + g) * 12;
            mma_f16_s(sA0, sA1, qa, Kg[kA + tid], Kg[kA + 4 + tid]);
            mma_f16_s(sB0, sB1, qa, Kg[kB + tid], Kg[kB + 4 + tid]);
            const __half2 e0 = h2exp2(bits2h(sA0));
            const __half2 e1 = h2exp2(bits2h(sA1));
            const __half2 e2 = h2exp2(bits2h(sB0));
            const __half2 e3 = h2exp2(bits2h(sB1));
            lh0 = __hadd2(lh0, __hadd2(e0, e2));
            lh1 = __hadd2(lh1, __hadd2(e1, e3));
            uint32_t pa[4];
            pa[0] = h2bits(e0);
            pa[1] = h2bits(e1);
            pa[2] = h2bits(e2);
            pa[3] = h2bits(e3);
            const int vb = 8 * u + tid;
            mma_f16(o0, pa, Vg[g * 68 + vb],       Vg[g * 68 + 4 + vb]);
            mma_f16(o1, pa, Vg[(g + 8) * 68 + vb], Vg[(g + 8) * 68 + 4 + vb]);
        }
        const float2 f0 = __half22float2(lh0);
        const float2 f1 = __half22float2(lh1);
        l0 += f0.x + f0.y;
        l1 += f1.x + f1.y;

        __syncthreads();
    }

    l0 += __shfl_xor_sync(0xffffffffu, l0, 1);
    l0 += __shfl_xor_sync(0xffffffffu, l0, 2);
    l1 += __shfl_xor_sync(0xffffffffu, l1, 1);
    l1 += __shfl_xor_sync(0xffffffffu, l1, 2);
    const float i0 = 1.f / l0;
    const float i1 = 1.f / l1;

    __half* O0 = g_attn_h + (qbase + w * 16 + g) * HD + h * D;
    __half* O1 = O0 + 8 * HD;
    *(__half2*)(O0 + 2 * tid)     = __floats2half2_rn(o0[0] * i0, o0[1] * i0);
    *(__half2*)(O1 + 2 * tid)     = __floats2half2_rn(o0[2] * i1, o0[3] * i1);
    *(__half2*)(O0 + 2 * tid + 8) = __floats2half2_rn(o1[0] * i0, o1[1] * i0);
    *(__half2*)(O1 + 2 * tid + 8) = __floats2half2_rn(o1[2] * i1, o1[3] * i1);
}

// ---------------------------------------------------------------------------
// Kernel 3: out projection, 16 nodes/block, 256 threads (8 warps — 2x MLP
// vs R15; R16 proved this path numerically at 1.0947e-05). Warp w owns a
// 16-col n-slice. All s/out traffic float4. Wo register-resident.
// ---------------------------------------------------------------------------
__global__ __launch_bounds__(256) void out_kernel(
        const float* __restrict__ s,
        const float* __restrict__ bo,
        const float* __restrict__ gamma, const float* __restrict__ beta,
        float* __restrict__ out) {
    __shared__ __align__(16) __half osm[16 * SA];     // O tile, 84-word rows
    __shared__ __align__(16) float vals[16 * 132];    // s + attn_out (f32)
    __shared__ float mus[16], ivs[16];

    const int nb = blockIdx.x * 16;
    const int t = threadIdx.x;       // 0..255
    const int w = t >> 5, lane = t & 31;   // warp w: n-cols [16w, 16w+16)
    const int g = lane >> 2, tid = lane & 3;

    // stage O tile via cp.async (256 chunks, 1/thread)
    const uint32_t ob = smem_u32(osm);
    {
        const int r = t >> 4, c = t & 15;
        cp16(ob + r * 336 + c * 16, g_attn_h + (nb + r) * HD + c * 8);
    }
    cp_commit();

    // Wo B-fragments to registers: 32 independent LDG.32 per thread
    uint32_t wreg[8][4];   // [ks][bt*2 + {0,1}], bt in {0,1}
    {
        const uint32_t* wg = (const uint32_t*)g_Wo_t;
#pragma unroll
        for (int ks = 0; ks < 8; ks++) {
#pragma unroll
            for (int bt = 0; bt < 2; bt++) {
                const uint32_t* br = wg + (w * 16 + bt * 8 + g) * 64 + ks * 8;
                wreg[ks][bt * 2]     = __ldg(br + tid);
                wreg[ks][bt * 2 + 1] = __ldg(br + 4 + tid);
            }
        }
    }

    // residual s: 512 float4, 2/thread
    for (int i = t; i < 512; i += 256) {
        const int node = i >> 5, c4 = i & 31;
        const float4 s4 = ((const float4*)(s + (nb + node) * NS))[c4];
        *(float4*)(vals + node * 132 + c4 * 4) = s4;
    }

    cp_wait<0>();
    __syncthreads();

    const uint32_t* cw = (const uint32_t*)osm;
    float cq[2][4];
#pragma unroll
    for (int i = 0; i < 2; i++)
#pragma unroll
        for (int j = 0; j < 4; j++) cq[i][j] = 0.f;

#pragma unroll
    for (int ks = 0; ks < 8; ks++) {
        uint32_t a[4];
        a[0] = cw[g * 84 + ks * 8 + tid];
        a[1] = cw[(g + 8) * 84 + ks * 8 + tid];
        a[2] = cw[g * 84 + ks * 8 + 4 + tid];
        a[3] = cw[(g + 8) * 84 + ks * 8 + 4 + tid];
#pragma unroll
        for (int bt = 0; bt < 2; bt++) {
            mma_f16(cq[bt], a, wreg[ks][bt * 2], wreg[ks][bt * 2 + 1]);
        }
    }

    // epilogue: vals += attn_out + bias
#pragma unroll
    for (int bt = 0; bt < 2; bt++) {
        const int c = w * 16 + bt * 8 + 2 * tid;
        const float b0 = bo[c], b1 = bo[c + 1];
        vals[g * 132 + c]           += cq[bt][0] + b0;
        vals[g * 132 + c + 1]       += cq[bt][1] + b1;
        vals[(g + 8) * 132 + c]     += cq[bt][2] + b0;
        vals[(g + 8) * 132 + c + 1] += cq[bt][3] + b1;
    }
    __syncthreads();

    // LayerNorm stats: warp w owns nodes 2w, 2w+1
#pragma unroll
    for (int jj = 0; jj < 2; jj++) {
        const int j = w * 2 + jj;
        float sv = 0.f, sq = 0.f;
#pragma unroll
        for (int c = 0; c < 4; c++) {
            const float x = vals[j * 132 + lane + 32 * c];
            sv += x;
            sq = fmaf(x, x, sq);
        }
#pragma unroll
        for (int off = 16; off > 0; off >>= 1) {
            sv += __shfl_xor_sync(0xffffffffu, sv, off);
            sq += __shfl_xor_sync(0xffffffffu, sq, off);
        }
        if (lane == 0) {
            const float mu = sv * (1.f / 128.f);
            mus[j] = mu;
            ivs[j] = rsqrtf(sq * (1.f / 128.f) - mu * mu + 1e-5f);
        }
    }
    __syncthreads();

    // normalize + store, float4 (2 per thread)
    for (int i = t; i < 512; i += 256) {
        const int node = i >> 5, c4 = i & 31;
        const float mu = mus[node], iv = ivs[node];
        const float4 vx = *(const float4*)(vals + node * 132 + c4 * 4);
        const float4 gm = ((const float4*)gamma)[c4];
        const float4 bt = ((const float4*)beta)[c4];
        float4 r;
        r.x = (vx.x - mu) * iv * gm.x + bt.x;
        r.y = (vx.y - mu) * iv * gm.y + bt.y;
        r.z = (vx.z - mu) * iv * gm.z + bt.z;
        r.w = (vx.w - mu) * iv * gm.w + bt.w;
        ((float4*)(out + (nb + node) * NS))[c4] = r;
    }
}

// ---------------------------------------------------------------------------
extern "C" void kernel_launch(void* const* d_in, const int* in_sizes, int n_in,
                              void* d_out, int out_size) {
    const float* s     = (const float*)d_in[0];
    const float* v     = (const float*)d_in[1];
    const float* Wq    = (const float*)d_in[2];
    const float* bq    = (const float*)d_in[3];
    const float* Wk    = (const float*)d_in[4];
    const float* bk    = (const float*)d_in[5];
    const float* Wv    = (const float*)d_in[6];
    const float* bv    = (const float*)d_in[7];
    const float* Wo    = (const float*)d_in[8];
    const float* bo    = (const float*)d_in[9];
    const float* gamma = (const float*)d_in[10];
    const float* beta  = (const float*)d_in[11];
    float* out = (float*)d_out;

    convw_kernel<<<256, 144>>>(Wq, Wk, Wv, Wo);
    proj_kernel<<<N_NODES / 32, 256>>>(s, v, bq, bk, bv, out);
    attn_kernel<<<dim3(N_NODES / 128, H), 256>>>();
    out_kernel<<<N_NODES / 16, 256>>>(s, bo, gamma, beta, out);
}